// round 5
// baseline (speedup 1.0000x reference)
#include <cuda_runtime.h>

#define H 1024
#define V 50257
#define LCTX 4096

#define NBLK 148            // <= SM count -> all blocks co-resident (safe sw barrier)
#define TPB  1024
#define NWARP (NBLK * 32)   // 4736 warps total
#define NROW_LOG 11         // ceil(V / NWARP)

// ---------------- device scratch (allocation-free, 16B aligned) ----------------
__device__ __align__(16) float g_e[LCTX];
__device__ __align__(16) float g_cat[2 * H];
__device__ __align__(16) float g_x[H];
__device__ __align__(16) float g_gh[3 * H];
__device__ __align__(16) float g_h[H];
__device__ float g_bm[NBLK];
__device__ float g_bs[NBLK];
__device__ unsigned g_bar_count = 0;
__device__ unsigned g_bar_gen   = 0;

__device__ __forceinline__ void grid_barrier() {
    __threadfence();
    __syncthreads();
    if (threadIdx.x == 0) {
        unsigned gen = *(volatile unsigned*)&g_bar_gen;
        if (atomicAdd(&g_bar_count, 1u) == NBLK - 1) {
            g_bar_count = 0;
            __threadfence();
            atomicExch(&g_bar_gen, gen + 1);
        } else {
            while (*(volatile unsigned*)&g_bar_gen == gen) {}
        }
        __threadfence();
    }
    __syncthreads();
}

__device__ __forceinline__ float warp_sum(float s) {
#pragma unroll
    for (int o = 16; o; o >>= 1) s += __shfl_xor_sync(0xffffffffu, s, o);
    return s;
}
__device__ __forceinline__ float warp_max(float s) {
#pragma unroll
    for (int o = 16; o; o >>= 1) s = fmaxf(s, __shfl_xor_sync(0xffffffffu, s, o));
    return s;
}

// ================= everything in ONE persistent kernel =================
__global__ void __launch_bounds__(TPB, 1)
fused_kernel(const int* __restrict__ y, const float* __restrict__ s_bef,
             const float* __restrict__ h_all, const float* __restrict__ emb_W,
             const float* __restrict__ alignW, const float* __restrict__ new_W,
             const float* __restrict__ new_b, const float* __restrict__ W_ih,
             const float* __restrict__ b_ih, const float* __restrict__ W_hh,
             const float* __restrict__ b_hh, const float* __restrict__ out_W,
             const float* __restrict__ out_b, float* __restrict__ out) {
    __shared__ float sbuf[2 * H];            // phase-dependent staging (8 KB)
    __shared__ float sred[33];
    __shared__ float smp[32], ssp[32];       // (max, sumexp) pair reduce

    const int t    = threadIdx.x;
    const int bid  = blockIdx.x;
    const int wid  = t >> 5;
    const int lane = t & 31;
    const int gw   = bid * 32 + wid;         // global warp id, 0..4735
    float4* sb4 = reinterpret_cast<float4*>(sbuf);

    // ---------- phase 1: e = h_all@Wh ; gh = W_hh@s_prev + b_hh ; emb ; zero ctx ----------
    if (t < 256)      sb4[t] = reinterpret_cast<const float4*>(alignW)[t];        // Wh
    else if (t < 512) sb4[t] = reinterpret_cast<const float4*>(s_bef)[t - 256];   // s_prev
    __syncthreads();

    if (bid == 1 && t < 256)
        reinterpret_cast<float4*>(g_cat)[t] =
            reinterpret_cast<const float4*>(emb_W)[(size_t)y[0] * 256 + t];
    if (bid == 2 && t < 256)
        reinterpret_cast<float4*>(g_cat)[256 + t] = make_float4(0.f, 0.f, 0.f, 0.f);

    for (int r = gw; r < LCTX + 3 * H; r += NWARP) {
        const float4 *row, *vec;
        if (r < LCTX) { row = reinterpret_cast<const float4*>(h_all) + (size_t)r * 256; vec = sb4; }
        else          { row = reinterpret_cast<const float4*>(W_hh) + (size_t)(r - LCTX) * 256; vec = sb4 + 256; }
        float s = 0.0f;
#pragma unroll
        for (int i = 0; i < 8; ++i) {
            float4 w = __ldg(&row[lane + i * 32]);
            float4 x = vec[lane + i * 32];
            s = fmaf(w.x, x.x, s); s = fmaf(w.y, x.y, s);
            s = fmaf(w.z, x.z, s); s = fmaf(w.w, x.w, s);
        }
        s = warp_sum(s);
        if (lane == 0) {
            if (r < LCTX) g_e[r] = s;
            else          g_gh[r - LCTX] = s + b_hh[r - LCTX];
        }
    }
    grid_barrier();

    // ---------- phase 2: softmax stats (redundant per block, L2-hot), ctx, a-out ----------
    float m = -1e30f;
#pragma unroll
    for (int k = 0; k < 4; ++k) m = fmaxf(m, g_e[k * 1024 + t]);
    m = warp_max(m);
    if (lane == 0) sred[wid] = m;
    __syncthreads();
    if (wid == 0) { float v = warp_max(sred[lane]); if (lane == 0) sred[32] = v; }
    __syncthreads();
    const float M = sred[32];
    float se = 0.0f;
#pragma unroll
    for (int k = 0; k < 4; ++k) se += expf(g_e[k * 1024 + t] - M);
    se = warp_sum(se);
    __syncthreads();
    if (lane == 0) sred[wid] = se;
    __syncthreads();
    if (wid == 0) { float v = warp_sum(sred[lane]); if (lane == 0) sred[32] = v; }
    __syncthreads();
    const float invS = 1.0f / sred[32];
    __syncthreads();   // done reading sred/sbuf before reuse

    if (bid < 32) {
        // ctx: block handles 128 l-rows, all H columns; h_all re-read is L2-hot
        const int l0 = bid * 128;
        if (t < 128) sbuf[t] = expf(g_e[l0 + t] - M) * invS;
        __syncthreads();
        const float* hp = h_all + (size_t)l0 * H + t;
        float acc = 0.0f;
#pragma unroll 8
        for (int l = 0; l < 128; ++l) acc = fmaf(sbuf[l], hp[(size_t)l * H], acc);
        atomicAdd(&g_cat[H + t], acc);
    } else if (bid < 36) {
        // attention weights to output slot (unaligned base -> scalar stores)
        int l = (bid - 32) * 1024 + t;
        out[V + H + l] = expf(g_e[l] - M) * invS;
    }
    grid_barrier();

    // ---------- phase 3: x = new_W @ [emb; c] + new_b ----------
    if (t < 512) sb4[t] = reinterpret_cast<const float4*>(g_cat)[t];
    __syncthreads();
    if (gw < H) {
        const float4* row = reinterpret_cast<const float4*>(new_W) + (size_t)gw * 512;
        float acc = 0.0f;
#pragma unroll
        for (int i = 0; i < 16; ++i) {
            float4 w = __ldg(&row[lane + i * 32]);
            float4 x = sb4[lane + i * 32];
            acc = fmaf(w.x, x.x, acc); acc = fmaf(w.y, x.y, acc);
            acc = fmaf(w.z, x.z, acc); acc = fmaf(w.w, x.w, acc);
        }
        acc = warp_sum(acc);
        if (lane == 0) g_x[gw] = acc + new_b[gw];
    }
    grid_barrier();

    // ---------- phase 4: gi = W_ih @ x + b_ih, fused GRU gates -> h_new ----------
    if (t < 256) sb4[t] = reinterpret_cast<const float4*>(g_x)[t];
    __syncthreads();
    if (gw < H) {
        float d[3];
#pragma unroll
        for (int g = 0; g < 3; ++g) {
            const float4* row = reinterpret_cast<const float4*>(W_ih) + (size_t)(gw + g * H) * 256;
            float acc = 0.0f;
#pragma unroll
            for (int i = 0; i < 8; ++i) {
                float4 w = __ldg(&row[lane + i * 32]);
                float4 x = sb4[lane + i * 32];
                acc = fmaf(w.x, x.x, acc); acc = fmaf(w.y, x.y, acc);
                acc = fmaf(w.z, x.z, acc); acc = fmaf(w.w, x.w, acc);
            }
            d[g] = warp_sum(acc);
        }
        if (lane == 0) {
            float r = 1.0f / (1.0f + expf(-(d[0] + b_ih[gw] + g_gh[gw])));
            float z = 1.0f / (1.0f + expf(-(d[1] + b_ih[gw + H] + g_gh[gw + H])));
            float n = tanhf(d[2] + b_ih[gw + 2 * H] + r * g_gh[gw + 2 * H]);
            float hv = (1.0f - z) * n + z * s_bef[gw];
            g_h[gw]   = hv;
            out[V + gw] = hv;
        }
    }
    grid_barrier();

    // ---------- phase 5: logits GEMV + fused log-softmax (values held in regs) ----------
    if (t < 256) sb4[t] = reinterpret_cast<const float4*>(g_h)[t];
    __syncthreads();

    float vals[NROW_LOG];
    float lm = -1e30f, ls = 0.0f;
#pragma unroll
    for (int k = 0; k < NROW_LOG; ++k) {
        const int r = gw + k * NWARP;
        float val = 0.0f;
        if (r < V) {
            const float4* Wr = reinterpret_cast<const float4*>(out_W) + (size_t)r * 256;
            float s = 0.0f;
#pragma unroll
            for (int i = 0; i < 8; ++i) {
                float4 w = __ldg(&Wr[lane + i * 32]);
                float4 x = sb4[lane + i * 32];
                s = fmaf(w.x, x.x, s); s = fmaf(w.y, x.y, s);
                s = fmaf(w.z, x.z, s); s = fmaf(w.w, x.w, s);
            }
            s = warp_sum(s);
            val = s + out_b[r];
            // online (max, sumexp) on lane 0
            if (lane == 0) {
                float nm = fmaxf(lm, val);
                ls = ls * expf(lm - nm) + expf(val - nm);
                lm = nm;
            }
        }
        vals[k] = val;
    }
    if (lane == 0) { smp[wid] = lm; ssp[wid] = ls; }
    __syncthreads();
    if (wid == 0) {
        float pm = smp[lane], ps = ssp[lane];
#pragma unroll
        for (int o = 16; o; o >>= 1) {
            float om = __shfl_xor_sync(0xffffffffu, pm, o);
            float os = __shfl_xor_sync(0xffffffffu, ps, o);
            float nm = fmaxf(pm, om);
            ps = ps * expf(pm - nm) + os * expf(om - nm);
            pm = nm;
        }
        if (lane == 0) { g_bm[bid] = pm; g_bs[bid] = ps; }
    }
    grid_barrier();

    // combine the 148 block pairs redundantly per block -> ln
    if (wid == 0) {
        float pm = -1e30f, ps = 0.0f;
        for (int i = lane; i < NBLK; i += 32) {
            float om = g_bm[i], os = g_bs[i];
            float nm = fmaxf(pm, om);
            ps = ps * expf(pm - nm) + os * expf(om - nm);
            pm = nm;
        }
#pragma unroll
        for (int o = 16; o; o >>= 1) {
            float om = __shfl_xor_sync(0xffffffffu, pm, o);
            float os = __shfl_xor_sync(0xffffffffu, ps, o);
            float nm = fmaxf(pm, om);
            ps = ps * expf(pm - nm) + os * expf(om - nm);
            pm = nm;
        }
        if (lane == 0) sred[0] = pm + logf(ps);
    }
    __syncthreads();
    const float ln = sred[0];

#pragma unroll
    for (int k = 0; k < NROW_LOG; ++k) {
        const int r = gw + k * NWARP;
        if (lane == 0 && r < V) out[r] = vals[k] - ln;
    }
}

// ================= launch: single kernel =================
extern "C" void kernel_launch(void* const* d_in, const int* in_sizes, int n_in,
                              void* d_out, int out_size) {
    const int*   y      = (const int*)d_in[0];
    const float* s_bef  = (const float*)d_in[1];
    const float* h_all  = (const float*)d_in[2];
    const float* emb_W  = (const float*)d_in[3];
    const float* alignW = (const float*)d_in[4];
    // d_in[5] align_b: uniform additive shift -> softmax-invariant, dropped
    const float* new_W  = (const float*)d_in[6];
    const float* new_b  = (const float*)d_in[7];
    const float* W_ih   = (const float*)d_in[8];
    const float* b_ih   = (const float*)d_in[9];
    const float* W_hh   = (const float*)d_in[10];
    const float* b_hh   = (const float*)d_in[11];
    const float* out_W  = (const float*)d_in[12];
    const float* out_b  = (const float*)d_in[13];
    float* out = (float*)d_out;  // [logp(V) | h_new(H) | a(L)]

    fused_kernel<<<NBLK, TPB>>>(y, s_bef, h_all, emb_W, alignW, new_W, new_b,
                                W_ih, b_ih, W_hh, b_hh, out_W, out_b, out);
}

// round 6
// speedup vs baseline: 1.0579x; 1.0579x over previous
#include <cuda_runtime.h>

#define H 1024
#define V 50257
#define LCTX 4096

#define NBLK 888            // 148 SMs x 6 co-resident 256-thr blocks -> sw barrier safe
#define TPB  256
#define NWARP (NBLK * 8)    // 7104 warps
#define NROW_LOG 8          // ceil(V / NWARP)

// ---------------- device scratch (allocation-free, 16B aligned) ----------------
__device__ __align__(16) float g_e[LCTX];
__device__ __align__(16) float g_cat[2 * H];
__device__ __align__(16) float g_x[H];
__device__ __align__(16) float g_gi[3 * H];
__device__ __align__(16) float g_gh[3 * H];
__device__ __align__(16) float g_h[H];
__device__ float g_bm[NBLK];
__device__ float g_bs[NBLK];
__device__ unsigned g_bar_count = 0;
__device__ unsigned g_bar_gen   = 0;

__device__ __forceinline__ void grid_barrier() {
    __threadfence();
    __syncthreads();
    if (threadIdx.x == 0) {
        unsigned gen = *(volatile unsigned*)&g_bar_gen;
        if (atomicAdd(&g_bar_count, 1u) == NBLK - 1) {
            g_bar_count = 0;
            __threadfence();
            atomicExch(&g_bar_gen, gen + 1);
        } else {
            while (*(volatile unsigned*)&g_bar_gen == gen) { __nanosleep(64); }
        }
        __threadfence();
    }
    __syncthreads();
}

__device__ __forceinline__ float warp_sum(float s) {
#pragma unroll
    for (int o = 16; o; o >>= 1) s += __shfl_xor_sync(0xffffffffu, s, o);
    return s;
}
__device__ __forceinline__ float warp_max(float s) {
#pragma unroll
    for (int o = 16; o; o >>= 1) s = fmaxf(s, __shfl_xor_sync(0xffffffffu, s, o));
    return s;
}
// online (max, sumexp) pair combine
__device__ __forceinline__ void pair_combine(float& m, float& s, float om, float os) {
    float nm = fmaxf(m, om);
    s = s * expf(m - nm) + os * expf(om - nm);
    m = nm;
}

// dot of row (C4 float4s) with shared vector, warp-wide
template <int C4>
__device__ __forceinline__ float row_dot(const float4* __restrict__ row,
                                         const float4* __restrict__ vec, int lane) {
    float s = 0.0f;
#pragma unroll
    for (int i = 0; i < C4 / 32; ++i) {
        float4 w = __ldg(&row[lane + i * 32]);
        float4 x = vec[lane + i * 32];
        s = fmaf(w.x, x.x, s); s = fmaf(w.y, x.y, s);
        s = fmaf(w.z, x.z, s); s = fmaf(w.w, x.w, s);
    }
    return warp_sum(s);
}

// ================= everything in ONE kernel, 6 blocks/SM guaranteed =================
__global__ void __launch_bounds__(TPB, 6)
fused_kernel(const int* __restrict__ y, const float* __restrict__ s_bef,
             const float* __restrict__ h_all, const float* __restrict__ emb_W,
             const float* __restrict__ alignW, const float* __restrict__ new_W,
             const float* __restrict__ new_b, const float* __restrict__ W_ih,
             const float* __restrict__ b_ih, const float* __restrict__ W_hh,
             const float* __restrict__ b_hh, const float* __restrict__ out_W,
             const float* __restrict__ out_b, float* __restrict__ out) {
    __shared__ float sbuf[2 * H];       // 8 KB staging
    __shared__ float sred[40];
    __shared__ float smp[8], ssp[8];

    const int t    = threadIdx.x;
    const int bid  = blockIdx.x;
    const int wid  = t >> 5;
    const int lane = t & 31;
    const int gw   = bid * 8 + wid;     // 0..7103
    float4* sb4 = reinterpret_cast<float4*>(sbuf);

    // ---------- phase 1: e = h_all@Wh ; gh = W_hh@s_prev + b_hh ; emb ; zero ctx ----------
    sb4[t]       = reinterpret_cast<const float4*>(alignW)[t];        // Wh
    sb4[256 + t] = reinterpret_cast<const float4*>(s_bef)[t];         // s_prev
    __syncthreads();

    if (bid == 1)
        reinterpret_cast<float4*>(g_cat)[t] =
            reinterpret_cast<const float4*>(emb_W)[(size_t)y[0] * 256 + t];
    if (bid == 2)
        reinterpret_cast<float4*>(g_cat)[256 + t] = make_float4(0.f, 0.f, 0.f, 0.f);

    for (int r = gw; r < LCTX + 3 * H; r += NWARP) {
        float s;
        if (r < LCTX)
            s = row_dot<256>(reinterpret_cast<const float4*>(h_all) + (size_t)r * 256, sb4, lane);
        else
            s = row_dot<256>(reinterpret_cast<const float4*>(W_hh) + (size_t)(r - LCTX) * 256, sb4 + 256, lane);
        if (lane == 0) {
            if (r < LCTX) g_e[r] = s;
            else          g_gh[r - LCTX] = s + b_hh[r - LCTX];
        }
    }
    grid_barrier();

    // ---------- phase 2: softmax stats (redundant per block, L2-hot) + ctx + a-out ----------
    float m = -1e30f;
#pragma unroll
    for (int k = 0; k < 16; ++k) m = fmaxf(m, g_e[k * 256 + t]);
    m = warp_max(m);
    if (lane == 0) sred[wid] = m;
    __syncthreads();
    if (wid == 0) { float v = (lane < 8) ? sred[lane] : -1e30f; v = warp_max(v); if (lane == 0) sred[32] = v; }
    __syncthreads();
    const float M = sred[32];
    float se = 0.0f;
#pragma unroll
    for (int k = 0; k < 16; ++k) se += expf(g_e[k * 256 + t] - M);
    se = warp_sum(se);
    __syncthreads();
    if (lane == 0) sred[wid] = se;
    __syncthreads();
    if (wid == 0) { float v = (lane < 8) ? sred[lane] : 0.0f; v = warp_sum(v); if (lane == 0) sred[33] = v; }
    __syncthreads();
    const float invS = 1.0f / sred[33];
    __syncthreads();

    if (bid < 512) {
        // ctx: block = 32 l-rows x 256 cols (L2-hot h_all re-read)
        const int jg = bid & 3, l0 = (bid >> 2) * 32;
        if (t < 32) sbuf[t] = expf(g_e[l0 + t] - M) * invS;
        __syncthreads();
        const int j = jg * 256 + t;
        const float* hp = h_all + (size_t)l0 * H + j;
        float acc = 0.0f;
#pragma unroll 8
        for (int l = 0; l < 32; ++l) acc = fmaf(sbuf[l], hp[(size_t)l * H], acc);
        atomicAdd(&g_cat[H + j], acc);
    } else if (bid < 528) {
        int l = (bid - 512) * 256 + t;
        out[V + H + l] = expf(g_e[l] - M) * invS;   // attention weights output
    }
    grid_barrier();

    // ---------- phase 3: x = new_W @ [emb; c] + new_b  (1024 warps) ----------
    if (bid < 128) {
        sb4[t]       = reinterpret_cast<const float4*>(g_cat)[t];
        sb4[256 + t] = reinterpret_cast<const float4*>(g_cat)[256 + t];
        __syncthreads();
        const int r = gw;  // 0..1023
        float acc = row_dot<512>(reinterpret_cast<const float4*>(new_W) + (size_t)r * 512, sb4, lane);
        if (lane == 0) g_x[r] = acc + new_b[r];
    }
    grid_barrier();

    // ---------- phase 4a: gi = W_ih @ x + b_ih  (3072 warps in parallel) ----------
    if (bid < 384) {
        sb4[t] = reinterpret_cast<const float4*>(g_x)[t];
        __syncthreads();
        const int r = gw;  // 0..3071
        float acc = row_dot<256>(reinterpret_cast<const float4*>(W_ih) + (size_t)r * 256, sb4, lane);
        if (lane == 0) g_gi[r] = acc + b_ih[r];
    }
    grid_barrier();

    // ---------- phase 4b: GRU gates elementwise -> h_new ----------
    if (bid < 4) {
        const int i = bid * 256 + t;  // 0..1023
        float r = 1.0f / (1.0f + expf(-(g_gi[i] + g_gh[i])));
        float z = 1.0f / (1.0f + expf(-(g_gi[H + i] + g_gh[H + i])));
        float n = tanhf(g_gi[2 * H + i] + r * g_gh[2 * H + i]);
        float hv = (1.0f - z) * n + z * s_bef[i];
        g_h[i]    = hv;
        out[V + i] = hv;
    }
    grid_barrier();

    // ---------- phase 5: logits GEMV (206 MB stream) + online (max,sumexp) ----------
    sb4[t] = reinterpret_cast<const float4*>(g_h)[t];
    __syncthreads();

    float lm = -1e30f, ls = 0.0f;
#pragma unroll
    for (int k = 0; k < NROW_LOG; ++k) {
        const int r = gw + k * NWARP;
        if (r < V) {
            float s = row_dot<256>(reinterpret_cast<const float4*>(out_W) + (size_t)r * 256, sb4, lane);
            float val = s + out_b[r];           // uniform across warp (xor reduce)
            if (lane == 0) out[r] = val;        // raw logit; fixed up after barrier
            pair_combine(lm, ls, val, 1.0f);    // maintained uniformly on all lanes
        }
    }
    if (lane == 0) { smp[wid] = lm; ssp[wid] = ls; }
    __syncthreads();
    if (wid == 0) {
        float pm = (lane < 8) ? smp[lane] : -1e30f;
        float ps = (lane < 8) ? ssp[lane] : 0.0f;
#pragma unroll
        for (int o = 4; o; o >>= 1) {
            float om = __shfl_xor_sync(0xffffffffu, pm, o);
            float os = __shfl_xor_sync(0xffffffffu, ps, o);
            pair_combine(pm, ps, om, os);
        }
        if (lane == 0) { g_bm[bid] = pm; g_bs[bid] = ps; }
    }
    grid_barrier();

    // ---------- phase 6: combine 888 block pairs redundantly; subtract ln ----------
    {
        float pm = -1e30f, ps = 0.0f;
        for (int i = t; i < NBLK; i += TPB) pair_combine(pm, ps, g_bm[i], g_bs[i]);
#pragma unroll
        for (int o = 16; o; o >>= 1) {
            float om = __shfl_xor_sync(0xffffffffu, pm, o);
            float os = __shfl_xor_sync(0xffffffffu, ps, o);
            pair_combine(pm, ps, om, os);
        }
        if (lane == 0) { smp[wid] = pm; ssp[wid] = ps; }
        __syncthreads();
        if (wid == 0) {
            float qm = (lane < 8) ? smp[lane] : -1e30f;
            float qs = (lane < 8) ? ssp[lane] : 0.0f;
#pragma unroll
            for (int o = 4; o; o >>= 1) {
                float om = __shfl_xor_sync(0xffffffffu, qm, o);
                float os = __shfl_xor_sync(0xffffffffu, qs, o);
                pair_combine(qm, qs, om, os);
            }
            if (lane == 0) sred[34] = qm + logf(qs);
        }
        __syncthreads();
        const float ln = sred[34];
        const int i = bid * TPB + t;           // L2-hot read-modify-write
        if (i < V) out[i] -= ln;
    }
}

// ================= launch: single kernel =================
extern "C" void kernel_launch(void* const* d_in, const int* in_sizes, int n_in,
                              void* d_out, int out_size) {
    const int*   y      = (const int*)d_in[0];
    const float* s_bef  = (const float*)d_in[1];
    const float* h_all  = (const float*)d_in[2];
    const float* emb_W  = (const float*)d_in[3];
    const float* alignW = (const float*)d_in[4];
    // d_in[5] align_b: uniform additive shift -> softmax-invariant, dropped
    const float* new_W  = (const float*)d_in[6];
    const float* new_b  = (const float*)d_in[7];
    const float* W_ih   = (const float*)d_in[8];
    const float* b_ih   = (const float*)d_in[9];
    const float* W_hh   = (const float*)d_in[10];
    const float* b_hh   = (const float*)d_in[11];
    const float* out_W  = (const float*)d_in[12];
    const float* out_b  = (const float*)d_in[13];
    float* out = (float*)d_out;  // [logp(V) | h_new(H) | a(L)]

    fused_kernel<<<NBLK, TPB>>>(y, s_bef, h_all, emb_W, alignW, new_W, new_b,
                                W_ih, b_ih, W_hh, b_hh, out_W, out_b, out);
}

// round 7
// speedup vs baseline: 1.1978x; 1.1322x over previous
#include <cuda_runtime.h>

#define H 1024
#define V 50257
#define LCTX 4096

#define NBLK 592            // 148 SMs x 4 co-resident 256-thr blocks (regs<=64) -> sw barrier safe
#define TPB  256
#define NWARP (NBLK * 8)    // 4736 warps
#define NROW_LOG 11         // ceil(V / NWARP), consecutive rows per warp

// ---------------- device scratch (allocation-free, 16B aligned) ----------------
__device__ __align__(16) float g_e[LCTX];
__device__ __align__(16) float g_cat[2 * H];
__device__ __align__(16) float g_x[H];
__device__ __align__(16) float g_gi[3 * H];
__device__ __align__(16) float g_gh[3 * H];
__device__ __align__(16) float g_h[H];
__device__ float g_bm[NBLK];
__device__ float g_bs[NBLK];
__device__ unsigned g_bar_count = 0;
__device__ unsigned g_bar_gen   = 0;

__device__ __forceinline__ void grid_barrier() {
    __threadfence();
    __syncthreads();
    if (threadIdx.x == 0) {
        unsigned gen = *(volatile unsigned*)&g_bar_gen;
        if (atomicAdd(&g_bar_count, 1u) == NBLK - 1) {
            g_bar_count = 0;
            __threadfence();
            atomicExch(&g_bar_gen, gen + 1);
        } else {
            while (*(volatile unsigned*)&g_bar_gen == gen) { __nanosleep(64); }
        }
        __threadfence();
    }
    __syncthreads();
}

__device__ __forceinline__ float warp_sum(float s) {
#pragma unroll
    for (int o = 16; o; o >>= 1) s += __shfl_xor_sync(0xffffffffu, s, o);
    return s;
}
__device__ __forceinline__ float warp_max(float s) {
#pragma unroll
    for (int o = 16; o; o >>= 1) s = fmaxf(s, __shfl_xor_sync(0xffffffffu, s, o));
    return s;
}
__device__ __forceinline__ void pair_combine(float& m, float& s, float om, float os) {
    float nm = fmaxf(m, om);
    s = s * expf(m - nm) + os * expf(om - nm);
    m = nm;
}

template <int C4>
__device__ __forceinline__ float row_dot(const float4* __restrict__ row,
                                         const float4* __restrict__ vec, int lane) {
    float s = 0.0f;
#pragma unroll
    for (int i = 0; i < C4 / 32; ++i) {
        float4 w = __ldg(&row[lane + i * 32]);
        float4 x = vec[lane + i * 32];
        s = fmaf(w.x, x.x, s); s = fmaf(w.y, x.y, s);
        s = fmaf(w.z, x.z, s); s = fmaf(w.w, x.w, s);
    }
    return warp_sum(s);
}

// ================= everything in ONE kernel, 4 blocks/SM =================
__global__ void __launch_bounds__(TPB, 4)
fused_kernel(const int* __restrict__ y, const float* __restrict__ s_bef,
             const float* __restrict__ h_all, const float* __restrict__ emb_W,
             const float* __restrict__ alignW, const float* __restrict__ new_W,
             const float* __restrict__ new_b, const float* __restrict__ W_ih,
             const float* __restrict__ b_ih, const float* __restrict__ W_hh,
             const float* __restrict__ b_hh, const float* __restrict__ out_W,
             const float* __restrict__ out_b, float* __restrict__ out) {
    __shared__ float sbuf[2 * H];
    __shared__ float sred[40];
    __shared__ float smp[8], ssp[8];

    const int t    = threadIdx.x;
    const int bid  = blockIdx.x;
    const int wid  = t >> 5;
    const int lane = t & 31;
    const int gw   = bid * 8 + wid;     // 0..4735
    float4* sb4 = reinterpret_cast<float4*>(sbuf);

    // ---------- phase 1: e = h_all@Wh ; gh = W_hh@s_prev + b_hh ; emb ; zero ctx ----------
    sb4[t]       = reinterpret_cast<const float4*>(alignW)[t];        // Wh
    sb4[256 + t] = reinterpret_cast<const float4*>(s_bef)[t];         // s_prev
    __syncthreads();

    if (bid == 1)
        reinterpret_cast<float4*>(g_cat)[t] =
            reinterpret_cast<const float4*>(emb_W)[(size_t)y[0] * 256 + t];
    if (bid == 2)
        reinterpret_cast<float4*>(g_cat)[256 + t] = make_float4(0.f, 0.f, 0.f, 0.f);

    for (int r = gw; r < LCTX + 3 * H; r += NWARP) {
        float s;
        if (r < LCTX)
            s = row_dot<256>(reinterpret_cast<const float4*>(h_all) + (size_t)r * 256, sb4, lane);
        else
            s = row_dot<256>(reinterpret_cast<const float4*>(W_hh) + (size_t)(r - LCTX) * 256, sb4 + 256, lane);
        if (lane == 0) {
            if (r < LCTX) g_e[r] = s;
            else          g_gh[r - LCTX] = s + b_hh[r - LCTX];
        }
    }
    grid_barrier();

    // ---------- phase 2: softmax stats (redundant per block, L2-hot) + ctx + a-out ----------
    float m = -1e30f;
#pragma unroll
    for (int k = 0; k < 16; ++k) m = fmaxf(m, g_e[k * 256 + t]);
    m = warp_max(m);
    if (lane == 0) sred[wid] = m;
    __syncthreads();
    if (wid == 0) { float v = (lane < 8) ? sred[lane] : -1e30f; v = warp_max(v); if (lane == 0) sred[32] = v; }
    __syncthreads();
    const float M = sred[32];
    float se = 0.0f;
#pragma unroll
    for (int k = 0; k < 16; ++k) se += expf(g_e[k * 256 + t] - M);
    se = warp_sum(se);
    __syncthreads();
    if (lane == 0) sred[wid] = se;
    __syncthreads();
    if (wid == 0) { float v = (lane < 8) ? sred[lane] : 0.0f; v = warp_sum(v); if (lane == 0) sred[33] = v; }
    __syncthreads();
    const float invS = 1.0f / sred[33];
    __syncthreads();

    if (bid < 512) {
        // ctx: block = 32 l-rows x 256 cols; h_all re-read is L2-hot; no h_all duplication
        const int jg = bid & 3, l0 = (bid >> 2) * 32;
        if (t < 32) sbuf[t] = expf(g_e[l0 + t] - M) * invS;
        __syncthreads();
        const int j = jg * 256 + t;
        const float* hp = h_all + (size_t)l0 * H + j;
        float acc = 0.0f;
#pragma unroll 8
        for (int l = 0; l < 32; ++l) acc = fmaf(sbuf[l], hp[(size_t)l * H], acc);
        atomicAdd(&g_cat[H + j], acc);
    } else if (bid < 528) {
        int l = (bid - 512) * 256 + t;
        out[V + H + l] = expf(g_e[l] - M) * invS;   // attention weights output
    }
    grid_barrier();

    // ---------- phase 3: x = new_W @ [emb; c] + new_b ----------
    if (bid < 128) {
        sb4[t]       = reinterpret_cast<const float4*>(g_cat)[t];
        sb4[256 + t] = reinterpret_cast<const float4*>(g_cat)[256 + t];
        __syncthreads();
        float acc = row_dot<512>(reinterpret_cast<const float4*>(new_W) + (size_t)gw * 512, sb4, lane);
        if (lane == 0) g_x[gw] = acc + new_b[gw];
    }
    grid_barrier();

    // ---------- phase 4a: gi = W_ih @ x + b_ih ----------
    if (bid < 384) {
        sb4[t] = reinterpret_cast<const float4*>(g_x)[t];
        __syncthreads();
        float acc = row_dot<256>(reinterpret_cast<const float4*>(W_ih) + (size_t)gw * 256, sb4, lane);
        if (lane == 0) g_gi[gw] = acc + b_ih[gw];
    }
    grid_barrier();

    // ---------- phase 4b: GRU gates elementwise -> h_new ----------
    if (bid < 4) {
        const int i = bid * 256 + t;
        float r = 1.0f / (1.0f + expf(-(g_gi[i] + g_gh[i])));
        float z = 1.0f / (1.0f + expf(-(g_gi[H + i] + g_gh[H + i])));
        float n = tanhf(g_gi[2 * H + i] + r * g_gh[2 * H + i]);
        float hv = (1.0f - z) * n + z * s_bef[i];
        g_h[i]    = hv;
        out[V + i] = hv;
    }
    grid_barrier();

    // ---------- phase 5: logits GEMV, x in REGISTERS, 11 consecutive rows/warp ----------
    float4 xr[8];
#pragma unroll
    for (int i = 0; i < 8; ++i)
        xr[i] = reinterpret_cast<const float4*>(g_h)[lane + i * 32];

    const int r0 = gw * NROW_LOG;
    float vals[NROW_LOG];
    // pure LDG+FMA loop: independent accumulators, no shuffles, no LDS -> deep MLP
#pragma unroll
    for (int k = 0; k < NROW_LOG; ++k) {
        float s = 0.0f;
        const int r = r0 + k;
        if (r < V) {
            const float4* Wr = reinterpret_cast<const float4*>(out_W) + (size_t)r * 256;
#pragma unroll
            for (int i = 0; i < 8; ++i) {
                float4 w = __ldcs(&Wr[lane + i * 32]);
                s = fmaf(w.x, xr[i].x, s); s = fmaf(w.y, xr[i].y, s);
                s = fmaf(w.z, xr[i].z, s); s = fmaf(w.w, xr[i].w, s);
            }
        }
        vals[k] = s;
    }
    // deferred reductions + bias; vals become warp-uniform
#pragma unroll
    for (int k = 0; k < NROW_LOG; ++k) {
        vals[k] = warp_sum(vals[k]);
        if (r0 + k < V) vals[k] += out_b[r0 + k];
    }
    // online (max,sumexp) over this warp's rows
    float lm = -1e30f, ls = 0.0f;
#pragma unroll
    for (int k = 0; k < NROW_LOG; ++k)
        if (r0 + k < V) pair_combine(lm, ls, vals[k], 1.0f);

    if (lane == 0) { smp[wid] = lm; ssp[wid] = ls; }
    __syncthreads();
    if (wid == 0) {
        float pm = (lane < 8) ? smp[lane] : -1e30f;
        float ps = (lane < 8) ? ssp[lane] : 0.0f;
#pragma unroll
        for (int o = 4; o; o >>= 1) {
            float om = __shfl_xor_sync(0xffffffffu, pm, o);
            float os = __shfl_xor_sync(0xffffffffu, ps, o);
            pair_combine(pm, ps, om, os);
        }
        if (lane == 0) { g_bm[bid] = pm; g_bs[bid] = ps; }
    }
    grid_barrier();

    // ---------- phase 6: combine 592 block pairs redundantly; store final logp from regs ----------
    {
        float pm = -1e30f, ps = 0.0f;
        for (int i = t; i < NBLK; i += TPB) pair_combine(pm, ps, g_bm[i], g_bs[i]);
#pragma unroll
        for (int o = 16; o; o >>= 1) {
            float om = __shfl_xor_sync(0xffffffffu, pm, o);
            float os = __shfl_xor_sync(0xffffffffu, ps, o);
            pair_combine(pm, ps, om, os);
        }
        if (lane == 0) { smp[wid] = pm; ssp[wid] = ps; }
        __syncthreads();
        if (wid == 0) {
            float qm = (lane < 8) ? smp[lane] : -1e30f;
            float qs = (lane < 8) ? ssp[lane] : 0.0f;
#pragma unroll
            for (int o = 4; o; o >>= 1) {
                float om = __shfl_xor_sync(0xffffffffu, qm, o);
                float os = __shfl_xor_sync(0xffffffffu, qs, o);
                pair_combine(qm, qs, om, os);
            }
            if (lane == 0) sred[34] = qm + logf(qs);
        }
        __syncthreads();
        const float ln = sred[34];
        if (lane == 0) {
#pragma unroll
            for (int k = 0; k < NROW_LOG; ++k)
                if (r0 + k < V) out[r0 + k] = vals[k] - ln;   // only store of logits
        }
    }
}

// ================= launch: single kernel =================
extern "C" void kernel_launch(void* const* d_in, const int* in_sizes, int n_in,
                              void* d_out, int out_size) {
    const int*   y      = (const int*)d_in[0];
    const float* s_bef  = (const float*)d_in[1];
    const float* h_all  = (const float*)d_in[2];
    const float* emb_W  = (const float*)d_in[3];
    const float* alignW = (const float*)d_in[4];
    // d_in[5] align_b: uniform additive shift -> softmax-invariant, dropped
    const float* new_W  = (const float*)d_in[6];
    const float* new_b  = (const float*)d_in[7];
    const float* W_ih   = (const float*)d_in[8];
    const float* b_ih   = (const float*)d_in[9];
    const float* W_hh   = (const float*)d_in[10];
    const float* b_hh   = (const float*)d_in[11];
    const float* out_W  = (const float*)d_in[12];
    const float* out_b  = (const float*)d_in[13];
    float* out = (float*)d_out;  // [logp(V) | h_new(H) | a(L)]

    fused_kernel<<<NBLK, TPB>>>(y, s_bef, h_all, emb_W, alignW, new_W, new_b,
                                W_ih, b_ih, W_hh, b_hh, out_W, out_b, out);
}